// round 5
// baseline (speedup 1.0000x reference)
#include <cuda_runtime.h>
#include <cstdint>

// out[b, 0:128]   = x[b, :]                       for b < B
// out[b, 128:256] = sum_{e: dst[e]==b} x[src[e]]
//
// Pipeline:
//   memset:  zero per-row counters + overflow counter (graph memset nodes).
//   K1 bin:  ELL binning by destination (scalar, one edge per thread).
//   K2 main: one warp per row. Sources consumed in chunks of 8: all 8
//            predicated gathers issued BEFORE any accumulation, so each warp
//            keeps ~8 loads in flight (vs 1 with a naive load+add loop).
//            Fused copy of x[b]; overflow rows (deg > SLOTS) scan the
//            overflow list in-warp. Plain STG.128 stores, no atomics.

#define NFEAT   128
#define ROW_OUT 256
#define MAX_E   640000
#define B_MAX   65536
#define SLOTS   32
#define CHUNK   8

__device__ int  g_cnt[B_MAX];
__device__ int  g_ell[B_MAX * SLOTS];
__device__ int2 g_ovf[MAX_E];
__device__ int  g_ovf_count;

__global__ void bin_kernel(const int* __restrict__ ei, int E, int B) {
    int i = blockIdx.x * blockDim.x + threadIdx.x;
    if (i >= E) return;
    int d = __ldg(ei + E + i);
    if ((unsigned)d < (unsigned)B) {
        int s = __ldg(ei + i);
        int k = atomicAdd(&g_cnt[d], 1);
        if (k < SLOTS) {
            g_ell[d * SLOTS + k] = s;
        } else {
            int p = atomicAdd(&g_ovf_count, 1);
            g_ovf[p] = make_int2(s, d);
        }
    }
}

__global__ __launch_bounds__(256)
void main_kernel(const float* __restrict__ x,
                 float* __restrict__ out,
                 int B) {
    int warp = (blockIdx.x * blockDim.x + threadIdx.x) >> 5;
    int lane = threadIdx.x & 31;
    if (warp >= B) return;
    int b = warp;

    int c_raw = g_cnt[b];
    int c = c_raw < SLOTS ? c_raw : SLOTS;

    // Coalesced preload of this row's source list (one slot per lane).
    int src_l = (lane < c) ? g_ell[b * SLOTS + lane] : 0;

    // Own row load issued early; it overlaps the gather chunks below.
    float4 mine = __ldg(reinterpret_cast<const float4*>(
                            x + (size_t)b * NFEAT) + lane);

    float4 acc = make_float4(0.f, 0.f, 0.f, 0.f);

    #pragma unroll
    for (int k0 = 0; k0 < SLOTS; k0 += CHUNK) {
        if (k0 >= c) break;
        // Phase 1: issue all CHUNK gathers (predicated) before any add.
        float4 v[CHUNK];
        #pragma unroll
        for (int j = 0; j < CHUNK; j++) {
            int se = __shfl_sync(0xFFFFFFFFu, src_l, k0 + j);
            if (k0 + j < c) {
                v[j] = __ldg(reinterpret_cast<const float4*>(
                                 x + (size_t)se * NFEAT) + lane);
            } else {
                v[j] = make_float4(0.f, 0.f, 0.f, 0.f);
            }
        }
        // Phase 2: accumulate.
        #pragma unroll
        for (int j = 0; j < CHUNK; j++) {
            acc.x += v[j].x; acc.y += v[j].y;
            acc.z += v[j].z; acc.w += v[j].w;
        }
    }

    // Rare path: degree exceeded SLOTS -> extras live in the overflow list.
    if (c_raw > SLOTS) {
        int n = g_ovf_count;
        for (int e = 0; e < n; e++) {
            int2 ed = g_ovf[e];
            if (ed.y == b) {
                float4 v = __ldg(reinterpret_cast<const float4*>(
                                     x + (size_t)ed.x * NFEAT) + lane);
                acc.x += v.x; acc.y += v.y; acc.z += v.z; acc.w += v.w;
            }
        }
    }

    float4* orow = reinterpret_cast<float4*>(out + (size_t)b * ROW_OUT);
    orow[lane]               = mine;
    orow[(NFEAT / 4) + lane] = acc;
}

extern "C" void kernel_launch(void* const* d_in, const int* in_sizes, int n_in,
                              void* d_out, int out_size) {
    const float* x        = (const float*)d_in[0];
    const int*   edge_idx = (const int*)d_in[1];
    float*       out      = (float*)d_out;

    int B = out_size / ROW_OUT;          // 50000
    int E = in_sizes[1] / 2;             // 640000

    // Zero counters via graph-capturable memset nodes.
    void* p_cnt = nullptr;
    void* p_ovfc = nullptr;
    cudaGetSymbolAddress(&p_cnt, g_cnt);
    cudaGetSymbolAddress(&p_ovfc, g_ovf_count);
    cudaMemsetAsync(p_cnt, 0, (size_t)B * sizeof(int));
    cudaMemsetAsync(p_ovfc, 0, sizeof(int));

    {   // K1: ELL binning (one edge per thread)
        int threads = 256;
        int blocks = (E + threads - 1) / threads;
        bin_kernel<<<blocks, threads>>>(edge_idx, E, B);
    }
    {   // K2: main fused gather-accumulate-store, one warp per row
        int threads = 256;                          // 8 warps/block
        int blocks = (B + 7) / 8;
        main_kernel<<<blocks, threads>>>(x, out, B);
    }
}

// round 6
// speedup vs baseline: 1.0990x; 1.0990x over previous
#include <cuda_runtime.h>
#include <cstdint>

// out[b, 0:128]   = x[b, :]                       for b < B
// out[b, 128:256] = sum_{e: dst[e]==b} x[src[e]]
//
// Pipeline:
//   memset:  zero per-row counters + overflow counter (graph memset nodes).
//   K1 bin:  ELL binning by destination, 2 independent edges per thread.
//   K2 main: one warp per row; sources consumed in chunks of 4 (all 4
//            gathers issued before any add -> MLP≈4 at ~40 regs, keeping
//            occupancy at the 75% level). Fused copy of x[b]; overflow
//            rows (deg > SLOTS) scan the overflow list in-warp.
//            Plain STG.128 stores, no atomics in the main path.

#define NFEAT   128
#define ROW_OUT 256
#define MAX_E   640000
#define B_MAX   65536
#define SLOTS   32
#define CHUNK   4

__device__ int  g_cnt[B_MAX];
__device__ int  g_ell[B_MAX * SLOTS];
__device__ int2 g_ovf[MAX_E];
__device__ int  g_ovf_count;

__global__ void bin_kernel(const int* __restrict__ ei, int E, int B) {
    int half = E >> 1;
    int i = blockIdx.x * blockDim.x + threadIdx.x;
    if (i >= half) return;
    int i2 = i + half;

    // Two independent edge chains per thread -> 2x memory-level parallelism.
    int d0 = __ldg(ei + E + i);
    int d1 = __ldg(ei + E + i2);
    int s0 = __ldg(ei + i);
    int s1 = __ldg(ei + i2);

    if ((unsigned)d0 < (unsigned)B) {
        int k = atomicAdd(&g_cnt[d0], 1);
        if (k < SLOTS) g_ell[d0 * SLOTS + k] = s0;
        else           g_ovf[atomicAdd(&g_ovf_count, 1)] = make_int2(s0, d0);
    }
    if ((unsigned)d1 < (unsigned)B) {
        int k = atomicAdd(&g_cnt[d1], 1);
        if (k < SLOTS) g_ell[d1 * SLOTS + k] = s1;
        else           g_ovf[atomicAdd(&g_ovf_count, 1)] = make_int2(s1, d1);
    }
}

__global__ __launch_bounds__(256)
void main_kernel(const float* __restrict__ x,
                 float* __restrict__ out,
                 int B) {
    int warp = (blockIdx.x * blockDim.x + threadIdx.x) >> 5;
    int lane = threadIdx.x & 31;
    if (warp >= B) return;
    int b = warp;

    int c_raw = g_cnt[b];
    int c = c_raw < SLOTS ? c_raw : SLOTS;

    // Coalesced preload of this row's source list (one slot per lane).
    int src_l = (lane < c) ? g_ell[b * SLOTS + lane] : 0;

    // Own row load issued early; overlaps the gather chunks below.
    float4 mine = __ldg(reinterpret_cast<const float4*>(
                            x + (size_t)b * NFEAT) + lane);

    float4 acc = make_float4(0.f, 0.f, 0.f, 0.f);

    #pragma unroll
    for (int k0 = 0; k0 < SLOTS; k0 += CHUNK) {
        if (k0 >= c) break;
        // Phase 1: issue all CHUNK gathers before any accumulation.
        float4 v[CHUNK];
        #pragma unroll
        for (int j = 0; j < CHUNK; j++) {
            int se = __shfl_sync(0xFFFFFFFFu, src_l, k0 + j);
            if (k0 + j < c) {
                v[j] = __ldg(reinterpret_cast<const float4*>(
                                 x + (size_t)se * NFEAT) + lane);
            } else {
                v[j] = make_float4(0.f, 0.f, 0.f, 0.f);
            }
        }
        // Phase 2: accumulate.
        #pragma unroll
        for (int j = 0; j < CHUNK; j++) {
            acc.x += v[j].x; acc.y += v[j].y;
            acc.z += v[j].z; acc.w += v[j].w;
        }
    }

    // Rare path: degree exceeded SLOTS -> extras live in the overflow list.
    if (c_raw > SLOTS) {
        int n = g_ovf_count;
        for (int e = 0; e < n; e++) {
            int2 ed = g_ovf[e];
            if (ed.y == b) {
                float4 v = __ldg(reinterpret_cast<const float4*>(
                                     x + (size_t)ed.x * NFEAT) + lane);
                acc.x += v.x; acc.y += v.y; acc.z += v.z; acc.w += v.w;
            }
        }
    }

    float4* orow = reinterpret_cast<float4*>(out + (size_t)b * ROW_OUT);
    orow[lane]               = mine;
    orow[(NFEAT / 4) + lane] = acc;
}

extern "C" void kernel_launch(void* const* d_in, const int* in_sizes, int n_in,
                              void* d_out, int out_size) {
    const float* x        = (const float*)d_in[0];
    const int*   edge_idx = (const int*)d_in[1];
    float*       out      = (float*)d_out;

    int B = out_size / ROW_OUT;          // 50000
    int E = in_sizes[1] / 2;             // 640000

    // Zero counters via graph-capturable memset nodes.
    void* p_cnt = nullptr;
    void* p_ovfc = nullptr;
    cudaGetSymbolAddress(&p_cnt, g_cnt);
    cudaGetSymbolAddress(&p_ovfc, g_ovf_count);
    cudaMemsetAsync(p_cnt, 0, (size_t)B * sizeof(int));
    cudaMemsetAsync(p_ovfc, 0, sizeof(int));

    {   // K1: ELL binning (2 independent edges per thread)
        int half = E >> 1;
        int threads = 256;
        int blocks = (half + threads - 1) / threads;
        bin_kernel<<<blocks, threads>>>(edge_idx, E, B);
    }
    {   // K2: main fused gather-accumulate-store, one warp per row
        int threads = 256;                          // 8 warps/block
        int blocks = (B + 7) / 8;
        main_kernel<<<blocks, threads>>>(x, out, B);
    }
}